// round 7
// baseline (speedup 1.0000x reference)
#include <cuda_runtime.h>

static constexpr int K = 32;
static constexpr int ROWS_PER_THREAD = 8;   // one 256-bit store per plane
static constexpr int THREADS = 128;
static constexpr int ROWS_PER_CTA = THREADS * ROWS_PER_THREAD;  // 1024

__device__ __forceinline__ void ldg256(const float* p, float4& a, float4& b) {
    asm volatile("ld.global.nc.v8.f32 {%0,%1,%2,%3,%4,%5,%6,%7}, [%8];"
                 : "=f"(a.x), "=f"(a.y), "=f"(a.z), "=f"(a.w),
                   "=f"(b.x), "=f"(b.y), "=f"(b.z), "=f"(b.w)
                 : "l"(p));
}

__device__ __forceinline__ void stg256(float* p, const float4& a, const float4& b) {
    asm volatile("st.global.v8.f32 [%0], {%1,%2,%3,%4,%5,%6,%7,%8};"
                 :: "l"(p),
                    "f"(a.x), "f"(a.y), "f"(a.z), "f"(a.w),
                    "f"(b.x), "f"(b.y), "f"(b.z), "f"(b.w)
                 : "memory");
}

__global__ __launch_bounds__(THREADS, 8)
void bignet_kernel(const float* __restrict__ x,
                   const float4* __restrict__ W4,   // [K] float4
                   const float*  __restrict__ b,    // [K]
                   float* __restrict__ out,         // [K, N]
                   int N)
{
    __shared__ float4 sW[K];
    __shared__ float  sb[K];
    if (threadIdx.x < K) {
        sW[threadIdx.x] = W4[threadIdx.x];
        sb[threadIdx.x] = b[threadIdx.x];
    }
    __syncthreads();

    int t  = blockIdx.x * blockDim.x + threadIdx.x;
    int n0 = t * ROWS_PER_THREAD;
    if (n0 >= N) return;

    // Warp-granular plane rotation (4 warps/CTA): spread concurrent store
    // streams across all 32 output planes.
    int rot = ((blockIdx.x << 2) + (threadIdx.x >> 5)) & (K - 1);

    if (n0 + ROWS_PER_THREAD <= N) {
        // 8 rows = 128B contiguous per thread, via 4x LDG.256.
        float4 r[8];
        const float* xp = x + (size_t)n0 * 4;
        ldg256(xp +  0, r[0], r[1]);
        ldg256(xp +  8, r[2], r[3]);
        ldg256(xp + 16, r[4], r[5]);
        ldg256(xp + 24, r[6], r[7]);

        float* const outp = out + n0;

        #pragma unroll 4
        for (int k = 0; k < K; k++) {
            int kk = (k + rot) & (K - 1);
            float4 w  = sW[kk];
            float  bb = sb[kk];
            float4 o0, o1;
            o0.x = fmaf(r[0].x, w.x, fmaf(r[0].y, w.y, fmaf(r[0].z, w.z, fmaf(r[0].w, w.w, bb))));
            o0.y = fmaf(r[1].x, w.x, fmaf(r[1].y, w.y, fmaf(r[1].z, w.z, fmaf(r[1].w, w.w, bb))));
            o0.z = fmaf(r[2].x, w.x, fmaf(r[2].y, w.y, fmaf(r[2].z, w.z, fmaf(r[2].w, w.w, bb))));
            o0.w = fmaf(r[3].x, w.x, fmaf(r[3].y, w.y, fmaf(r[3].z, w.z, fmaf(r[3].w, w.w, bb))));
            o1.x = fmaf(r[4].x, w.x, fmaf(r[4].y, w.y, fmaf(r[4].z, w.z, fmaf(r[4].w, w.w, bb))));
            o1.y = fmaf(r[5].x, w.x, fmaf(r[5].y, w.y, fmaf(r[5].z, w.z, fmaf(r[5].w, w.w, bb))));
            o1.z = fmaf(r[6].x, w.x, fmaf(r[6].y, w.y, fmaf(r[6].z, w.z, fmaf(r[6].w, w.w, bb))));
            o1.w = fmaf(r[7].x, w.x, fmaf(r[7].y, w.y, fmaf(r[7].z, w.z, fmaf(r[7].w, w.w, bb))));
            stg256(outp + (size_t)kk * N, o0, o1);
        }
    } else {
        // Tail path: per-row scalar stores.
        for (int rr = 0; rr < ROWS_PER_THREAD; rr++) {
            int n = n0 + rr;
            if (n >= N) break;
            const float* xr = x + (size_t)n * 4;
            float x0 = xr[0], x1 = xr[1], x2 = xr[2], x3 = xr[3];
            #pragma unroll
            for (int k = 0; k < K; k++) {
                float4 w  = sW[k];
                float  bb = sb[k];
                float  o  = fmaf(x0, w.x, fmaf(x1, w.y, fmaf(x2, w.z, fmaf(x3, w.w, bb))));
                out[(size_t)k * N + n] = o;
            }
        }
    }
}

extern "C" void kernel_launch(void* const* d_in, const int* in_sizes, int n_in,
                              void* d_out, int out_size)
{
    const float* x = (const float*)d_in[0];   // [N, 4]
    const float* W = (const float*)d_in[1];   // [K, 1, 4]
    const float* b = (const float*)d_in[2];   // [K, 1]
    float* out = (float*)d_out;               // [K, N, 1]

    int N = in_sizes[0] / 4;

    int threads_needed = (N + ROWS_PER_THREAD - 1) / ROWS_PER_THREAD;
    int blocks = (threads_needed + THREADS - 1) / THREADS;

    bignet_kernel<<<blocks, THREADS>>>(
        x, (const float4*)W, b, out, N);
}